// round 14
// baseline (speedup 1.0000x reference)
#include <cuda_runtime.h>
#include <cuda.h>

#define NBLK   8192                    // tiles; tile = 8 input rows / 128 out pixels
#define GRIDSZ (148 * 10)

__device__ unsigned int g_tile_ctr = 0u;
__device__ unsigned int g_done_ctr = 0u;

__device__ __forceinline__ unsigned int smem_u32(const void* p) {
    return (unsigned int)__cvta_generic_to_shared(p);
}

// Tile blk contiguous in input ([blk*4096, +4096) float4) and output
// ([blk*1024, +1024) float4). Warp w owns pooled row hl=w.
// smem (float4 units): row r, chunk c at r*8 + (c ^ (r&7))  == TMA SW128 atom.
// DOUBLE-BUFFERED: TMA store of tile i drains while tile i+1 is produced.
__global__ void __launch_bounds__(128) savgpool_spike_tma(
    const float* __restrict__ x,
    const float* __restrict__ thresh,
    const __grid_constant__ CUtensorMap tmap)
{
    __shared__ __align__(1024) float4 sp[2][128 * 8];   // 2 x 16 KB
    __shared__ unsigned int s_blk;

    const int t    = threadIdx.x;
    const int lane = t & 31;
    const int w    = t >> 5;
    const float th = __ldg(thresh);
    const float4* __restrict__ x4 = (const float4*)x;

    if (t == 0) s_blk = atomicAdd(&g_tile_ctr, 1u);
    __syncthreads();
    unsigned int blk = s_blk;
    int p = 0;

    while (blk < NBLK) {
        const float4* __restrict__ xt = x4 + (size_t)blk * 4096 + (2 * w) * 512;
        float4* __restrict__ buf = sp[p];

        // ---- batch 0: 8 LDG.128 issued before anything blocks ----
        int wp0 = lane >> 3, c0 = lane & 7;
        int wp1 = wp0 + 4;
        const float4* p0 = xt + (2 * wp0) * 8 + c0;
        const float4* p1 = xt + (2 * wp1) * 8 + c0;
        float4 a0 = __ldcs(p0), b0 = __ldcs(p0 + 8);
        float4 e0 = __ldcs(p0 + 512), d0 = __ldcs(p0 + 520);
        float4 a1 = __ldcs(p1), b1 = __ldcs(p1 + 8);
        float4 e1 = __ldcs(p1 + 512), d1 = __ldcs(p1 + 520);

        // buffer p was last stored 2 tiles ago; allow 1 outstanding group
        if (t == 0)
            asm volatile("cp.async.bulk.wait_group.read 1;" ::: "memory");
        __syncthreads();

        {
            int r0 = w * 32 + wp0, r1 = w * 32 + wp1;
            float4 v0, v1;
            v0.x = (a0.x + b0.x + e0.x + d0.x) * 0.25f;
            v0.y = (a0.y + b0.y + e0.y + d0.y) * 0.25f;
            v0.z = (a0.z + b0.z + e0.z + d0.z) * 0.25f;
            v0.w = (a0.w + b0.w + e0.w + d0.w) * 0.25f;
            v1.x = (a1.x + b1.x + e1.x + d1.x) * 0.25f;
            v1.y = (a1.y + b1.y + e1.y + d1.y) * 0.25f;
            v1.z = (a1.z + b1.z + e1.z + d1.z) * 0.25f;
            v1.w = (a1.w + b1.w + e1.w + d1.w) * 0.25f;
            buf[r0 * 8 + (c0 ^ (r0 & 7))] = v0;
            buf[r1 * 8 + (c0 ^ (r1 & 7))] = v1;
        }

        // ---- batches 1..3 ----
        #pragma unroll
        for (int it2 = 1; it2 < 4; it2++) {
            int idx0 = (2 * it2) * 32 + lane;
            int idx1 = idx0 + 32;
            int wq0 = idx0 >> 3, cq0 = idx0 & 7;
            int wq1 = idx1 >> 3, cq1 = idx1 & 7;
            const float4* q0 = xt + (2 * wq0) * 8 + cq0;
            const float4* q1 = xt + (2 * wq1) * 8 + cq1;
            float4 ax0 = __ldcs(q0), bx0 = __ldcs(q0 + 8);
            float4 ex0 = __ldcs(q0 + 512), dx0 = __ldcs(q0 + 520);
            float4 ax1 = __ldcs(q1), bx1 = __ldcs(q1 + 8);
            float4 ex1 = __ldcs(q1 + 512), dx1 = __ldcs(q1 + 520);
            int r0 = w * 32 + wq0, r1 = w * 32 + wq1;
            float4 v0, v1;
            v0.x = (ax0.x + bx0.x + ex0.x + dx0.x) * 0.25f;
            v0.y = (ax0.y + bx0.y + ex0.y + dx0.y) * 0.25f;
            v0.z = (ax0.z + bx0.z + ex0.z + dx0.z) * 0.25f;
            v0.w = (ax0.w + bx0.w + ex0.w + dx0.w) * 0.25f;
            v1.x = (ax1.x + bx1.x + ex1.x + dx1.x) * 0.25f;
            v1.y = (ax1.y + bx1.y + ex1.y + dx1.y) * 0.25f;
            v1.z = (ax1.z + bx1.z + ex1.z + dx1.z) * 0.25f;
            v1.w = (ax1.w + bx1.w + ex1.w + dx1.w) * 0.25f;
            buf[r0 * 8 + (cq0 ^ (r0 & 7))] = v0;
            buf[r1 * 8 + (cq1 ^ (r1 & 7))] = v1;
        }
        __syncwarp();

        // ---- phase 2: LIF recurrence in place (own row) ----
        {
            const int sw = t & 7;
            float4* row = &buf[t * 8];
            float u = 0.0f, s = 0.0f;
            #pragma unroll
            for (int c = 0; c < 8; c++) {
                float4 q = row[c ^ sw];
                float4 v;
                u = u - s * th + q.x;  s = (u > 0.0f) ? 1.0f : 0.0f;  v.x = s;
                u = u - s * th + q.y;  s = (u > 0.0f) ? 1.0f : 0.0f;  v.y = s;
                u = u - s * th + q.z;  s = (u > 0.0f) ? 1.0f : 0.0f;  v.z = s;
                u = u - s * th + q.w;  s = (u > 0.0f) ? 1.0f : 0.0f;  v.w = s;
                row[c ^ sw] = v;
            }
        }
        asm volatile("fence.proxy.async.shared::cta;" ::: "memory");

        if (t == 0) s_blk = atomicAdd(&g_tile_ctr, 1u);   // prefetch next tile
        __syncthreads();          // spikes + s_blk visible everywhere

        if (t == 0) {
            asm volatile(
                "cp.async.bulk.tensor.2d.global.shared::cta.tile.bulk_group "
                "[%0, {%1, %2}], [%3];"
                :: "l"(&tmap), "r"(0), "r"((int)(blk * 128)), "r"(smem_u32(buf))
                : "memory");
            asm volatile("cp.async.bulk.commit_group;" ::: "memory");
        }
        blk = s_blk;
        p ^= 1;
    }

    if (t == 0) {
        asm volatile("cp.async.bulk.wait_group 0;" ::: "memory");  // drain stores
        __threadfence();
        // Self-reset: last block to finish restores counters for next replay.
        unsigned int d = atomicAdd(&g_done_ctr, 1u);
        if (d == GRIDSZ - 1) {
            atomicExch(&g_tile_ctr, 0u);
            atomicExch(&g_done_ctr, 0u);
        }
    }
}

// ---------------- Fallback (R11-style, no TMA needed) ----------------
__global__ void __launch_bounds__(128) savgpool_spike_fb(
    const float* __restrict__ x,
    const float* __restrict__ thresh,
    float* __restrict__ out)
{
    __shared__ float4 sp[128 * 8];
    __shared__ unsigned int s_blk;
    const int t = threadIdx.x, lane = t & 31, w = t >> 5;
    const float th = __ldg(thresh);
    const float4* __restrict__ x4 = (const float4*)x;
    float4* __restrict__ o4 = (float4*)out;

    for (;;) {
        if (t == 0) s_blk = atomicAdd(&g_tile_ctr, 1u);
        __syncthreads();
        unsigned int blk = s_blk;
        if (blk >= NBLK) break;
        const float4* __restrict__ xt = x4 + (size_t)blk * 4096 + (2 * w) * 512;
        float4* __restrict__ ot = o4 + (size_t)blk * 1024 + w * 256;
        #pragma unroll
        for (int it2 = 0; it2 < 4; it2++) {
            int idx0 = (2 * it2) * 32 + lane, idx1 = idx0 + 32;
            int wp0 = idx0 >> 3, cc0 = idx0 & 7, wp1 = idx1 >> 3, cc1 = idx1 & 7;
            const float4* p0 = xt + (2 * wp0) * 8 + cc0;
            const float4* p1 = xt + (2 * wp1) * 8 + cc1;
            float4 a0 = __ldcs(p0), b0 = __ldcs(p0 + 8), e0 = __ldcs(p0 + 512), d0 = __ldcs(p0 + 520);
            float4 a1 = __ldcs(p1), b1 = __ldcs(p1 + 8), e1 = __ldcs(p1 + 512), d1 = __ldcs(p1 + 520);
            int r0 = w * 32 + wp0, r1 = w * 32 + wp1;
            float4 v0, v1;
            v0.x = (a0.x+b0.x+e0.x+d0.x)*0.25f; v0.y = (a0.y+b0.y+e0.y+d0.y)*0.25f;
            v0.z = (a0.z+b0.z+e0.z+d0.z)*0.25f; v0.w = (a0.w+b0.w+e0.w+d0.w)*0.25f;
            v1.x = (a1.x+b1.x+e1.x+d1.x)*0.25f; v1.y = (a1.y+b1.y+e1.y+d1.y)*0.25f;
            v1.z = (a1.z+b1.z+e1.z+d1.z)*0.25f; v1.w = (a1.w+b1.w+e1.w+d1.w)*0.25f;
            sp[r0 * 8 + (cc0 ^ (r0 & 7))] = v0;
            sp[r1 * 8 + (cc1 ^ (r1 & 7))] = v1;
        }
        __syncwarp();
        {
            const int sw = t & 7;
            float4* row = &sp[t * 8];
            float u = 0.0f, s = 0.0f;
            #pragma unroll
            for (int c = 0; c < 8; c++) {
                float4 q = row[c ^ sw]; float4 v;
                u = u - s*th + q.x; s = (u > 0.0f) ? 1.0f : 0.0f; v.x = s;
                u = u - s*th + q.y; s = (u > 0.0f) ? 1.0f : 0.0f; v.y = s;
                u = u - s*th + q.z; s = (u > 0.0f) ? 1.0f : 0.0f; v.z = s;
                u = u - s*th + q.w; s = (u > 0.0f) ? 1.0f : 0.0f; v.w = s;
                row[c ^ sw] = v;
            }
        }
        __syncwarp();
        #pragma unroll
        for (int it = 0; it < 8; it++) {
            int cl = it * 32 + lane;
            int r = w * 32 + (cl >> 3), c = cl & 7;
            __stcs(ot + cl, sp[r * 8 + (c ^ (r & 7))]);
        }
        __syncthreads();
    }
    if (t == 0) {
        __threadfence();
        unsigned int d = atomicAdd(&g_done_ctr, 1u);
        if (d == GRIDSZ - 1) {
            atomicExch(&g_tile_ctr, 0u);
            atomicExch(&g_done_ctr, 0u);
        }
    }
}

extern "C" void kernel_launch(void* const* d_in, const int* in_sizes, int n_in,
                              void* d_out, int out_size)
{
    const float* x      = (const float*)d_in[0];
    const float* thresh = (const float*)d_in[1];
    float* out          = (float*)d_out;

    typedef CUresult (*EncodeFn)(CUtensorMap*, CUtensorMapDataType, cuuint32_t, void*,
                                 const cuuint64_t*, const cuuint64_t*, const cuuint32_t*,
                                 const cuuint32_t*, CUtensorMapInterleave, CUtensorMapSwizzle,
                                 CUtensorMapL2promotion, CUtensorMapFloatOOBfill);
    void* fnp = nullptr;
    cudaDriverEntryPointQueryResult qr = cudaDriverEntryPointSymbolNotFound;
    cudaGetDriverEntryPointByVersion("cuTensorMapEncodeTiled", &fnp, 12000,
                                     cudaEnableDefault, &qr);
    bool ok = false;
    CUtensorMap tmap;
    if (fnp && qr == cudaDriverEntryPointSuccess) {
        cuuint64_t dims[2]    = {32, (cuuint64_t)NBLK * 128};
        cuuint64_t strides[1] = {128};                  // bytes between rows
        cuuint32_t box[2]     = {32, 128};              // 128B x 128 rows = 16KB
        cuuint32_t estr[2]    = {1, 1};
        CUresult r = ((EncodeFn)fnp)(&tmap, CU_TENSOR_MAP_DATA_TYPE_FLOAT32, 2, out,
                                     dims, strides, box, estr,
                                     CU_TENSOR_MAP_INTERLEAVE_NONE,
                                     CU_TENSOR_MAP_SWIZZLE_128B,
                                     CU_TENSOR_MAP_L2_PROMOTION_L2_128B,
                                     CU_TENSOR_MAP_FLOAT_OOB_FILL_NONE);
        ok = (r == CUDA_SUCCESS);
    }

    if (ok)
        savgpool_spike_tma<<<GRIDSZ, 128>>>(x, thresh, tmap);
    else
        savgpool_spike_fb<<<GRIDSZ, 128>>>(x, thresh, out);
}

// round 15
// speedup vs baseline: 1.1896x; 1.1896x over previous
#include <cuda_runtime.h>
#include <cuda.h>

#define NBLK   8192                    // tiles; tile = 8 input rows / 128 out pixels
#define GRIDSZ (148 * 10)

__device__ unsigned int g_tile_ctr = 0u;
__device__ unsigned int g_done_ctr = 0u;

__device__ __forceinline__ unsigned int smem_u32(const void* p) {
    return (unsigned int)__cvta_generic_to_shared(p);
}

// ---------------- TMA-store version (R12 operating point: 64 regs, 16KB) ----
// Tile blk contiguous in input ([blk*4096, +4096) float4) and output
// ([blk*1024, +1024) float4). Warp w owns pooled row hl=w.
// smem (float4 units): row r, chunk c at r*8 + (c ^ (r&7))  == TMA SW128 atom.
// SINGLE buffer: R13 proved double-buffering evicts CTAs (regs/smem) and
// loses more DRAM overlap than the store-drain wait costs.
__global__ void __launch_bounds__(128) savgpool_spike_tma(
    const float* __restrict__ x,
    const float* __restrict__ thresh,
    const __grid_constant__ CUtensorMap tmap)
{
    __shared__ __align__(1024) float4 sp[128 * 8];   // 16 KB
    __shared__ unsigned int s_blk;

    const int t    = threadIdx.x;
    const int lane = t & 31;
    const int w    = t >> 5;
    const float th = __ldg(thresh);
    const float4* __restrict__ x4 = (const float4*)x;

    if (t == 0) s_blk = atomicAdd(&g_tile_ctr, 1u);
    __syncthreads();
    unsigned int blk = s_blk;

    while (blk < NBLK) {
        const float4* __restrict__ xt = x4 + (size_t)blk * 4096 + (2 * w) * 512;

        // ---- batch 0: issue 8 LDG.128 BEFORE the smem-reuse wait ----
        int wp0 = lane >> 3, c0 = lane & 7;
        int wp1 = wp0 + 4;
        const float4* p0 = xt + (2 * wp0) * 8 + c0;
        const float4* p1 = xt + (2 * wp1) * 8 + c0;
        float4 a0 = __ldcs(p0), b0 = __ldcs(p0 + 8);
        float4 e0 = __ldcs(p0 + 512), d0 = __ldcs(p0 + 520);
        float4 a1 = __ldcs(p1), b1 = __ldcs(p1 + 8);
        float4 e1 = __ldcs(p1 + 512), d1 = __ldcs(p1 + 520);

        // previous tile's TMA store must finish READING smem before any STS
        if (t == 0)
            asm volatile("cp.async.bulk.wait_group.read 0;" ::: "memory");
        __syncthreads();

        {
            int r0 = w * 32 + wp0, r1 = w * 32 + wp1;
            float4 v0, v1;
            v0.x = (a0.x + b0.x + e0.x + d0.x) * 0.25f;
            v0.y = (a0.y + b0.y + e0.y + d0.y) * 0.25f;
            v0.z = (a0.z + b0.z + e0.z + d0.z) * 0.25f;
            v0.w = (a0.w + b0.w + e0.w + d0.w) * 0.25f;
            v1.x = (a1.x + b1.x + e1.x + d1.x) * 0.25f;
            v1.y = (a1.y + b1.y + e1.y + d1.y) * 0.25f;
            v1.z = (a1.z + b1.z + e1.z + d1.z) * 0.25f;
            v1.w = (a1.w + b1.w + e1.w + d1.w) * 0.25f;
            sp[r0 * 8 + (c0 ^ (r0 & 7))] = v0;
            sp[r1 * 8 + (c0 ^ (r1 & 7))] = v1;
        }

        // ---- batches 1..3 ----
        #pragma unroll
        for (int it2 = 1; it2 < 4; it2++) {
            int idx0 = (2 * it2) * 32 + lane;
            int idx1 = idx0 + 32;
            int wq0 = idx0 >> 3, cq0 = idx0 & 7;
            int wq1 = idx1 >> 3, cq1 = idx1 & 7;
            const float4* q0 = xt + (2 * wq0) * 8 + cq0;
            const float4* q1 = xt + (2 * wq1) * 8 + cq1;
            float4 ax0 = __ldcs(q0), bx0 = __ldcs(q0 + 8);
            float4 ex0 = __ldcs(q0 + 512), dx0 = __ldcs(q0 + 520);
            float4 ax1 = __ldcs(q1), bx1 = __ldcs(q1 + 8);
            float4 ex1 = __ldcs(q1 + 512), dx1 = __ldcs(q1 + 520);
            int r0 = w * 32 + wq0, r1 = w * 32 + wq1;
            float4 v0, v1;
            v0.x = (ax0.x + bx0.x + ex0.x + dx0.x) * 0.25f;
            v0.y = (ax0.y + bx0.y + ex0.y + dx0.y) * 0.25f;
            v0.z = (ax0.z + bx0.z + ex0.z + dx0.z) * 0.25f;
            v0.w = (ax0.w + bx0.w + ex0.w + dx0.w) * 0.25f;
            v1.x = (ax1.x + bx1.x + ex1.x + dx1.x) * 0.25f;
            v1.y = (ax1.y + bx1.y + ex1.y + dx1.y) * 0.25f;
            v1.z = (ax1.z + bx1.z + ex1.z + dx1.z) * 0.25f;
            v1.w = (ax1.w + bx1.w + ex1.w + dx1.w) * 0.25f;
            sp[r0 * 8 + (cq0 ^ (r0 & 7))] = v0;
            sp[r1 * 8 + (cq1 ^ (r1 & 7))] = v1;
        }
        __syncwarp();

        // ---- phase 2: LIF recurrence in place (own row) ----
        {
            const int sw = t & 7;
            float4* row = &sp[t * 8];
            float u = 0.0f, s = 0.0f;
            #pragma unroll
            for (int c = 0; c < 8; c++) {
                float4 q = row[c ^ sw];
                float4 v;
                u = u - s * th + q.x;  s = (u > 0.0f) ? 1.0f : 0.0f;  v.x = s;
                u = u - s * th + q.y;  s = (u > 0.0f) ? 1.0f : 0.0f;  v.y = s;
                u = u - s * th + q.z;  s = (u > 0.0f) ? 1.0f : 0.0f;  v.z = s;
                u = u - s * th + q.w;  s = (u > 0.0f) ? 1.0f : 0.0f;  v.w = s;
                row[c ^ sw] = v;
            }
        }
        asm volatile("fence.proxy.async.shared::cta;" ::: "memory");

        if (t == 0) s_blk = atomicAdd(&g_tile_ctr, 1u);   // prefetch next tile
        __syncthreads();          // spikes + s_blk visible everywhere

        if (t == 0) {
            asm volatile(
                "cp.async.bulk.tensor.2d.global.shared::cta.tile.bulk_group "
                "[%0, {%1, %2}], [%3];"
                :: "l"(&tmap), "r"(0), "r"((int)(blk * 128)), "r"(smem_u32(sp))
                : "memory");
            asm volatile("cp.async.bulk.commit_group;" ::: "memory");
        }
        blk = s_blk;
    }

    if (t == 0) {
        asm volatile("cp.async.bulk.wait_group 0;" ::: "memory");  // drain stores
        __threadfence();
        // Self-reset: last block restores counters for the next graph replay.
        unsigned int d = atomicAdd(&g_done_ctr, 1u);
        if (d == GRIDSZ - 1) {
            atomicExch(&g_tile_ctr, 0u);
            atomicExch(&g_done_ctr, 0u);
        }
    }
}

// ---------------- Fallback (no TMA available) ----------------
__global__ void __launch_bounds__(128) savgpool_spike_fb(
    const float* __restrict__ x,
    const float* __restrict__ thresh,
    float* __restrict__ out)
{
    __shared__ float4 sp[128 * 8];
    __shared__ unsigned int s_blk;
    const int t = threadIdx.x, lane = t & 31, w = t >> 5;
    const float th = __ldg(thresh);
    const float4* __restrict__ x4 = (const float4*)x;
    float4* __restrict__ o4 = (float4*)out;

    for (;;) {
        if (t == 0) s_blk = atomicAdd(&g_tile_ctr, 1u);
        __syncthreads();
        unsigned int blk = s_blk;
        if (blk >= NBLK) break;
        const float4* __restrict__ xt = x4 + (size_t)blk * 4096 + (2 * w) * 512;
        float4* __restrict__ ot = o4 + (size_t)blk * 1024 + w * 256;
        #pragma unroll
        for (int it2 = 0; it2 < 4; it2++) {
            int idx0 = (2 * it2) * 32 + lane, idx1 = idx0 + 32;
            int wp0 = idx0 >> 3, cc0 = idx0 & 7, wp1 = idx1 >> 3, cc1 = idx1 & 7;
            const float4* p0 = xt + (2 * wp0) * 8 + cc0;
            const float4* p1 = xt + (2 * wp1) * 8 + cc1;
            float4 a0 = __ldcs(p0), b0 = __ldcs(p0 + 8), e0 = __ldcs(p0 + 512), d0 = __ldcs(p0 + 520);
            float4 a1 = __ldcs(p1), b1 = __ldcs(p1 + 8), e1 = __ldcs(p1 + 512), d1 = __ldcs(p1 + 520);
            int r0 = w * 32 + wp0, r1 = w * 32 + wp1;
            float4 v0, v1;
            v0.x = (a0.x+b0.x+e0.x+d0.x)*0.25f; v0.y = (a0.y+b0.y+e0.y+d0.y)*0.25f;
            v0.z = (a0.z+b0.z+e0.z+d0.z)*0.25f; v0.w = (a0.w+b0.w+e0.w+d0.w)*0.25f;
            v1.x = (a1.x+b1.x+e1.x+d1.x)*0.25f; v1.y = (a1.y+b1.y+e1.y+d1.y)*0.25f;
            v1.z = (a1.z+b1.z+e1.z+d1.z)*0.25f; v1.w = (a1.w+b1.w+e1.w+d1.w)*0.25f;
            sp[r0 * 8 + (cc0 ^ (r0 & 7))] = v0;
            sp[r1 * 8 + (cc1 ^ (r1 & 7))] = v1;
        }
        __syncwarp();
        {
            const int sw = t & 7;
            float4* row = &sp[t * 8];
            float u = 0.0f, s = 0.0f;
            #pragma unroll
            for (int c = 0; c < 8; c++) {
                float4 q = row[c ^ sw]; float4 v;
                u = u - s*th + q.x; s = (u > 0.0f) ? 1.0f : 0.0f; v.x = s;
                u = u - s*th + q.y; s = (u > 0.0f) ? 1.0f : 0.0f; v.y = s;
                u = u - s*th + q.z; s = (u > 0.0f) ? 1.0f : 0.0f; v.z = s;
                u = u - s*th + q.w; s = (u > 0.0f) ? 1.0f : 0.0f; v.w = s;
                row[c ^ sw] = v;
            }
        }
        __syncwarp();
        #pragma unroll
        for (int it = 0; it < 8; it++) {
            int cl = it * 32 + lane;
            int r = w * 32 + (cl >> 3), c = cl & 7;
            __stcs(ot + cl, sp[r * 8 + (c ^ (r & 7))]);
        }
        __syncthreads();
    }
    if (t == 0) {
        __threadfence();
        unsigned int d = atomicAdd(&g_done_ctr, 1u);
        if (d == GRIDSZ - 1) {
            atomicExch(&g_tile_ctr, 0u);
            atomicExch(&g_done_ctr, 0u);
        }
    }
}

extern "C" void kernel_launch(void* const* d_in, const int* in_sizes, int n_in,
                              void* d_out, int out_size)
{
    const float* x      = (const float*)d_in[0];
    const float* thresh = (const float*)d_in[1];
    float* out          = (float*)d_out;

    typedef CUresult (*EncodeFn)(CUtensorMap*, CUtensorMapDataType, cuuint32_t, void*,
                                 const cuuint64_t*, const cuuint64_t*, const cuuint32_t*,
                                 const cuuint32_t*, CUtensorMapInterleave, CUtensorMapSwizzle,
                                 CUtensorMapL2promotion, CUtensorMapFloatOOBfill);
    void* fnp = nullptr;
    cudaDriverEntryPointQueryResult qr = cudaDriverEntryPointSymbolNotFound;
    cudaGetDriverEntryPointByVersion("cuTensorMapEncodeTiled", &fnp, 12000,
                                     cudaEnableDefault, &qr);
    bool ok = false;
    CUtensorMap tmap;
    if (fnp && qr == cudaDriverEntryPointSuccess) {
        cuuint64_t dims[2]    = {32, (cuuint64_t)NBLK * 128};
        cuuint64_t strides[1] = {128};                  // bytes between rows
        cuuint32_t box[2]     = {32, 128};              // 128B x 128 rows = 16KB
        cuuint32_t estr[2]    = {1, 1};
        CUresult r = ((EncodeFn)fnp)(&tmap, CU_TENSOR_MAP_DATA_TYPE_FLOAT32, 2, out,
                                     dims, strides, box, estr,
                                     CU_TENSOR_MAP_INTERLEAVE_NONE,
                                     CU_TENSOR_MAP_SWIZZLE_128B,
                                     CU_TENSOR_MAP_L2_PROMOTION_L2_128B,
                                     CU_TENSOR_MAP_FLOAT_OOB_FILL_NONE);
        ok = (r == CUDA_SUCCESS);
    }

    if (ok)
        savgpool_spike_tma<<<GRIDSZ, 128>>>(x, thresh, tmap);
    else
        savgpool_spike_fb<<<GRIDSZ, 128>>>(x, thresh, out);
}